// round 13
// baseline (speedup 1.0000x reference)
#include <cuda_runtime.h>
#include <cuda_fp16.h>
#include <math.h>

#define BATCH 8
#define H 1024
#define W 1024
#define NWIN 5
#define PADY 64
#define ROWS (H + 2 * PADY)   // 1152 rows per (win,batch) image in scratch
#define NIMG (NWIN * BATCH)   // 40

__device__ __constant__ int c_radii[NWIN] = {3, 7, 15, 31, 63};
// launch big windows first (z=0 -> w=4) so long blocks don't form a tail
__device__ __constant__ int c_worder[NWIN] = {4, 3, 2, 1, 0};

// Scratch: horizontal window sums (sum x, sum x^2) packed as half2, with
// PADY zero rows above and below each image so the vertical pass needs no
// bounds checks. Pad rows are NEVER written; __device__ globals are
// zero-initialized at module load, so they remain zero deterministically.
__device__ __half2 g_hsums[(size_t)NIMG * ROWS * W];

// ---------------------------------------------------------------------------
// Pass A: 256 threads, 4 consecutive pixels/thread. float4 load, per-thread
// serial prefix + warp scan + block combine. Prefix in smem padded every 16
// entries (conflict-free stride-4 reads). Each window emits 4 half2 pixels
// as one uint4 store. One block per (row, batch).
// ---------------------------------------------------------------------------
#define HPB 256
#define PIDX(e) ((e) + ((e) >> 4))

__global__ __launch_bounds__(HPB) void hpass_kernel(const float* __restrict__ x,
                                                    uint4* __restrict__ hsums) {
    const int y = blockIdx.x;
    const int b = blockIdx.y;
    const int t = threadIdx.x;
    const int lane = t & 31;
    const int wid = t >> 5;

    __shared__ float2 s_warp[8];
    __shared__ float2 s_pref[PIDX(W - 1) + 1];   // padded

    const float4 v4 = reinterpret_cast<const float4*>(
        x + ((size_t)b * H + y) * W)[t];

    float px0 = v4.x,        py0 = v4.x * v4.x;
    float px1 = px0 + v4.y,  py1 = py0 + v4.y * v4.y;
    float px2 = px1 + v4.z,  py2 = py1 + v4.z * v4.z;
    float px3 = px2 + v4.w,  py3 = py2 + v4.w * v4.w;

    float tx = px3, ty = py3;
#pragma unroll
    for (int off = 1; off < 32; off <<= 1) {
        float ax = __shfl_up_sync(0xffffffffu, tx, off);
        float ay = __shfl_up_sync(0xffffffffu, ty, off);
        if (lane >= off) { tx += ax; ty += ay; }
    }
    if (lane == 31) s_warp[wid] = make_float2(tx, ty);
    __syncthreads();
    if (wid == 0 && lane < 8) {
        float2 w2 = s_warp[lane];
        float wx = w2.x, wy = w2.y;
#pragma unroll
        for (int off = 1; off < 8; off <<= 1) {
            float ax = __shfl_up_sync(0xffu, wx, off);
            float ay = __shfl_up_sync(0xffu, wy, off);
            if (lane >= off) { wx += ax; wy += ay; }
        }
        s_warp[lane] = make_float2(wx, wy);
    }
    __syncthreads();

    float bx = tx - px3, by = ty - py3;
    if (wid > 0) {
        float2 wb = s_warp[wid - 1];
        bx += wb.x; by += wb.y;
    }

    const int q0 = 4 * t;
    s_pref[PIDX(q0 + 0)] = make_float2(bx + px0, by + py0);
    s_pref[PIDX(q0 + 1)] = make_float2(bx + px1, by + py1);
    s_pref[PIDX(q0 + 2)] = make_float2(bx + px2, by + py2);
    s_pref[PIDX(q0 + 3)] = make_float2(bx + px3, by + py3);
    __syncthreads();

#pragma unroll
    for (int w = 0; w < NWIN; w++) {
        const int r = c_radii[w];
        unsigned int h[4];
#pragma unroll
        for (int i = 0; i < 4; i++) {
            const int q = q0 + i;
            const int hi = min(q + r, W - 1);
            float2 s = s_pref[PIDX(hi)];
            if (q > r) {
                float2 p = s_pref[PIDX(q - r - 1)];
                s.x -= p.x; s.y -= p.y;
            }
            __half2 hh = __floats2half2_rn(s.x, s.y);
            h[i] = *reinterpret_cast<unsigned int*>(&hh);
        }
        uint4 pack = make_uint4(h[0], h[1], h[2], h[3]);
        hsums[((size_t)(w * BATCH + b) * ROWS + PADY + y) * (W / 4) + t] = pack;
    }
}

// ---------------------------------------------------------------------------
// Pass B: vertical sliding window + Sauvola epilogue (R8 structure, R8 math).
// Each thread owns 2 adjacent columns (8B uint2 loads); batches of BU rows
// load into register arrays first (16 loads in flight), then math. Uniform
// 3-D grid, compile-time constant loop bounds. YCHUNKS=8 -> 128-row chunks:
// halves priming waste for big windows AND the 1280-block grid fits in one
// wave at the regs=60 RF cap (~34 warps/SM).
// ---------------------------------------------------------------------------
#define TPB 128
#define XB4 (W / (2 * TPB))   // 4
#define YCHUNKS 8
#define YCHUNK (H / YCHUNKS)  // 128
#define BU 8                  // row batch (YCHUNK % BU == 0)

__global__ __launch_bounds__(TPB) void vpass_kernel(const __half2* __restrict__ hsums,
                                                    const float* __restrict__ kk,
                                                    const float* __restrict__ RR,
                                                    float* __restrict__ out) {
    const int xblk = blockIdx.x & (XB4 - 1);
    const int ychunk = blockIdx.x / XB4;
    const int b = blockIdx.y;
    const int w = c_worder[blockIdx.z];

    const int tx = xblk * TPB + threadIdx.x;   // uint2 index (2 cols)
    const int x0 = 2 * tx;
    const int x1 = x0 + 1;
    const int r = c_radii[w];
    const float kw = kk[w];
    const float invR = __frcp_rn(RR[w]);

    const uint2* col = reinterpret_cast<const uint2*>(
        hsums + ((size_t)(w * BATCH + b) * ROWS + PADY) * W) + tx;
    float* o = out + (((size_t)b * NWIN + w) * H) * W + x0;

    const float cnth0 = (float)(min(x0 + r, W - 1) - max(x0 - r, 0) + 1);
    const float cnth1 = (float)(min(x1 + r, W - 1) - max(x1 - r, 0) + 1);

    const int y0 = ychunk * YCHUNK;

    float sx0 = 0.f, sy0 = 0.f, sx1 = 0.f, sy1 = 0.f;

    // Prime: S = sum of rows [y0-r, y0+r) (pad rows are zero, no clamping).
#pragma unroll 4
    for (int yy = y0 - r; yy < y0 + r; yy++) {
        uint2 u = col[(size_t)yy * (W / 2)];
        float2 f0 = __half22float2(*reinterpret_cast<__half2*>(&u.x));
        float2 f1 = __half22float2(*reinterpret_cast<__half2*>(&u.y));
        sx0 += f0.x; sy0 += f0.y; sx1 += f1.x; sy1 += f1.y;
    }

    for (int yb = y0; yb < y0 + YCHUNK; yb += BU) {
        // ---- batch-load phase: 2*BU independent 8B loads ----
        uint2 ua[BU], us[BU];
#pragma unroll
        for (int j = 0; j < BU; j++) {
            ua[j] = col[(size_t)(yb + j + r) * (W / 2)];
            us[j] = col[(size_t)(yb + j - r) * (W / 2)];
        }
        // ---- math phase ----
#pragma unroll
        for (int j = 0; j < BU; j++) {
            const int y = yb + j;
            {
                float2 f0 = __half22float2(*reinterpret_cast<__half2*>(&ua[j].x));
                float2 f1 = __half22float2(*reinterpret_cast<__half2*>(&ua[j].y));
                sx0 += f0.x; sy0 += f0.y; sx1 += f1.x; sy1 += f1.y;
            }
            const float cntv = (float)(min(y + r, H - 1) - max(y - r, 0) + 1);
            const float inv0 = __frcp_rn(cnth0 * cntv);
            const float inv1 = __frcp_rn(cnth1 * cntv);
            const float mean0 = sx0 * inv0, m20 = sy0 * inv0;
            const float mean1 = sx1 * inv1, m21 = sy1 * inv1;
            const float var0 = fmaxf(fmaf(-mean0, mean0, m20), 1e-6f);
            const float var1 = fmaxf(fmaf(-mean1, mean1, m21), 1e-6f);
            const float dev0 = sqrtf(var0);
            const float dev1 = sqrtf(var1);
            float2 res;
            res.x = mean0 * fmaf(kw, fmaf(dev0, invR, -1.0f), 1.0f);
            res.y = mean1 * fmaf(kw, fmaf(dev1, invR, -1.0f), 1.0f);
            *reinterpret_cast<float2*>(o + (size_t)y * W) = res;
            {
                float2 f0 = __half22float2(*reinterpret_cast<__half2*>(&us[j].x));
                float2 f1 = __half22float2(*reinterpret_cast<__half2*>(&us[j].y));
                sx0 -= f0.x; sy0 -= f0.y; sx1 -= f1.x; sy1 -= f1.y;
            }
        }
    }
}

extern "C" void kernel_launch(void* const* d_in, const int* in_sizes, int n_in,
                              void* d_out, int out_size) {
    const float* x = (const float*)d_in[0];
    const float* k = (const float*)d_in[1];
    const float* R = (const float*)d_in[2];
    float* out = (float*)d_out;

    __half2* hsums;
    cudaGetSymbolAddress((void**)&hsums, g_hsums);

    dim3 gridA(H, BATCH);
    hpass_kernel<<<gridA, HPB>>>(x, reinterpret_cast<uint4*>(hsums));

    dim3 gridB(XB4 * YCHUNKS, BATCH, NWIN);
    vpass_kernel<<<gridB, TPB>>>(hsums, k, R, out);
}

// round 14
// speedup vs baseline: 1.0645x; 1.0645x over previous
#include <cuda_runtime.h>
#include <cuda_fp16.h>
#include <math.h>

#define BATCH 8
#define H 1024
#define W 1024
#define NWIN 5
#define PADY 64
#define ROWS (H + 2 * PADY)   // 1152 rows per (win,batch) image in scratch
#define NIMG (NWIN * BATCH)   // 40

__device__ __constant__ int c_radii[NWIN] = {3, 7, 15, 31, 63};
// launch big windows first (z=0 -> w=4) so long blocks don't form a tail
__device__ __constant__ int c_worder[NWIN] = {4, 3, 2, 1, 0};

// Scratch: horizontal window sums (sum x, sum x^2) packed as half2, with
// PADY zero rows above and below each image so the vertical pass needs no
// bounds checks. Pad rows are NEVER written; __device__ globals are
// zero-initialized at module load, so they remain zero deterministically.
__device__ __half2 g_hsums[(size_t)NIMG * ROWS * W];

// ---------------------------------------------------------------------------
// Pass A: 256 threads, 4 consecutive pixels/thread. float4 load, per-thread
// serial prefix + warp scan + block combine. Prefix in smem padded every 16
// entries (conflict-free stride-4 reads). Each window emits 4 half2 pixels
// as one uint4 store. One block per (row, batch).
// ---------------------------------------------------------------------------
#define HPB 256
#define PIDX(e) ((e) + ((e) >> 4))

__global__ __launch_bounds__(HPB) void hpass_kernel(const float* __restrict__ x,
                                                    uint4* __restrict__ hsums) {
    const int y = blockIdx.x;
    const int b = blockIdx.y;
    const int t = threadIdx.x;
    const int lane = t & 31;
    const int wid = t >> 5;

    __shared__ float2 s_warp[8];
    __shared__ float2 s_pref[PIDX(W - 1) + 1];   // padded

    const float4 v4 = reinterpret_cast<const float4*>(
        x + ((size_t)b * H + y) * W)[t];

    float px0 = v4.x,        py0 = v4.x * v4.x;
    float px1 = px0 + v4.y,  py1 = py0 + v4.y * v4.y;
    float px2 = px1 + v4.z,  py2 = py1 + v4.z * v4.z;
    float px3 = px2 + v4.w,  py3 = py2 + v4.w * v4.w;

    float tx = px3, ty = py3;
#pragma unroll
    for (int off = 1; off < 32; off <<= 1) {
        float ax = __shfl_up_sync(0xffffffffu, tx, off);
        float ay = __shfl_up_sync(0xffffffffu, ty, off);
        if (lane >= off) { tx += ax; ty += ay; }
    }
    if (lane == 31) s_warp[wid] = make_float2(tx, ty);
    __syncthreads();
    if (wid == 0 && lane < 8) {
        float2 w2 = s_warp[lane];
        float wx = w2.x, wy = w2.y;
#pragma unroll
        for (int off = 1; off < 8; off <<= 1) {
            float ax = __shfl_up_sync(0xffu, wx, off);
            float ay = __shfl_up_sync(0xffu, wy, off);
            if (lane >= off) { wx += ax; wy += ay; }
        }
        s_warp[lane] = make_float2(wx, wy);
    }
    __syncthreads();

    float bx = tx - px3, by = ty - py3;
    if (wid > 0) {
        float2 wb = s_warp[wid - 1];
        bx += wb.x; by += wb.y;
    }

    const int q0 = 4 * t;
    s_pref[PIDX(q0 + 0)] = make_float2(bx + px0, by + py0);
    s_pref[PIDX(q0 + 1)] = make_float2(bx + px1, by + py1);
    s_pref[PIDX(q0 + 2)] = make_float2(bx + px2, by + py2);
    s_pref[PIDX(q0 + 3)] = make_float2(bx + px3, by + py3);
    __syncthreads();

#pragma unroll
    for (int w = 0; w < NWIN; w++) {
        const int r = c_radii[w];
        unsigned int h[4];
#pragma unroll
        for (int i = 0; i < 4; i++) {
            const int q = q0 + i;
            const int hi = min(q + r, W - 1);
            float2 s = s_pref[PIDX(hi)];
            if (q > r) {
                float2 p = s_pref[PIDX(q - r - 1)];
                s.x -= p.x; s.y -= p.y;
            }
            __half2 hh = __floats2half2_rn(s.x, s.y);
            h[i] = *reinterpret_cast<unsigned int*>(&hh);
        }
        uint4 pack = make_uint4(h[0], h[1], h[2], h[3]);
        hsums[((size_t)(w * BATCH + b) * ROWS + PADY + y) * (W / 4) + t] = pack;
    }
}

// ---------------------------------------------------------------------------
// Pass B: vertical sliding window + Sauvola epilogue (byte-exact R8 structure
// and math). Each thread owns 2 adjacent columns (8B uint2 loads); batches
// of BU rows load into register arrays first (16 loads in flight), then
// math. Uniform 3-D grid, compile-time constant loop bounds.
// __launch_bounds__ min-blocks=10 caps regs at ~51 -> 40 warps/SM RF limit
// (up from 34 at regs=60).
// ---------------------------------------------------------------------------
#define TPB 128
#define XB4 (W / (2 * TPB))   // 4
#define YCHUNKS 16
#define YCHUNK (H / YCHUNKS)  // 64
#define BU 8                  // row batch (YCHUNK % BU == 0)

__global__ __launch_bounds__(TPB, 10) void vpass_kernel(const __half2* __restrict__ hsums,
                                                        const float* __restrict__ kk,
                                                        const float* __restrict__ RR,
                                                        float* __restrict__ out) {
    const int xblk = blockIdx.x & (XB4 - 1);
    const int ychunk = blockIdx.x / XB4;
    const int b = blockIdx.y;
    const int w = c_worder[blockIdx.z];

    const int tx = xblk * TPB + threadIdx.x;   // uint2 index (2 cols)
    const int x0 = 2 * tx;
    const int x1 = x0 + 1;
    const int r = c_radii[w];
    const float kw = kk[w];
    const float invR = __frcp_rn(RR[w]);

    const uint2* col = reinterpret_cast<const uint2*>(
        hsums + ((size_t)(w * BATCH + b) * ROWS + PADY) * W) + tx;
    float* o = out + (((size_t)b * NWIN + w) * H) * W + x0;

    const float cnth0 = (float)(min(x0 + r, W - 1) - max(x0 - r, 0) + 1);
    const float cnth1 = (float)(min(x1 + r, W - 1) - max(x1 - r, 0) + 1);

    const int y0 = ychunk * YCHUNK;

    float sx0 = 0.f, sy0 = 0.f, sx1 = 0.f, sy1 = 0.f;

    // Prime: S = sum of rows [y0-r, y0+r) (pad rows are zero, no clamping).
#pragma unroll 4
    for (int yy = y0 - r; yy < y0 + r; yy++) {
        uint2 u = col[(size_t)yy * (W / 2)];
        float2 f0 = __half22float2(*reinterpret_cast<__half2*>(&u.x));
        float2 f1 = __half22float2(*reinterpret_cast<__half2*>(&u.y));
        sx0 += f0.x; sy0 += f0.y; sx1 += f1.x; sy1 += f1.y;
    }

    for (int yb = y0; yb < y0 + YCHUNK; yb += BU) {
        // ---- batch-load phase: 2*BU independent 8B loads ----
        uint2 ua[BU], us[BU];
#pragma unroll
        for (int j = 0; j < BU; j++) {
            ua[j] = col[(size_t)(yb + j + r) * (W / 2)];
            us[j] = col[(size_t)(yb + j - r) * (W / 2)];
        }
        // ---- math phase ----
#pragma unroll
        for (int j = 0; j < BU; j++) {
            const int y = yb + j;
            {
                float2 f0 = __half22float2(*reinterpret_cast<__half2*>(&ua[j].x));
                float2 f1 = __half22float2(*reinterpret_cast<__half2*>(&ua[j].y));
                sx0 += f0.x; sy0 += f0.y; sx1 += f1.x; sy1 += f1.y;
            }
            const float cntv = (float)(min(y + r, H - 1) - max(y - r, 0) + 1);
            const float inv0 = __frcp_rn(cnth0 * cntv);
            const float inv1 = __frcp_rn(cnth1 * cntv);
            const float mean0 = sx0 * inv0, m20 = sy0 * inv0;
            const float mean1 = sx1 * inv1, m21 = sy1 * inv1;
            const float var0 = fmaxf(fmaf(-mean0, mean0, m20), 1e-6f);
            const float var1 = fmaxf(fmaf(-mean1, mean1, m21), 1e-6f);
            const float dev0 = sqrtf(var0);
            const float dev1 = sqrtf(var1);
            float2 res;
            res.x = mean0 * fmaf(kw, fmaf(dev0, invR, -1.0f), 1.0f);
            res.y = mean1 * fmaf(kw, fmaf(dev1, invR, -1.0f), 1.0f);
            *reinterpret_cast<float2*>(o + (size_t)y * W) = res;
            {
                float2 f0 = __half22float2(*reinterpret_cast<__half2*>(&us[j].x));
                float2 f1 = __half22float2(*reinterpret_cast<__half2*>(&us[j].y));
                sx0 -= f0.x; sy0 -= f0.y; sx1 -= f1.x; sy1 -= f1.y;
            }
        }
    }
}

extern "C" void kernel_launch(void* const* d_in, const int* in_sizes, int n_in,
                              void* d_out, int out_size) {
    const float* x = (const float*)d_in[0];
    const float* k = (const float*)d_in[1];
    const float* R = (const float*)d_in[2];
    float* out = (float*)d_out;

    __half2* hsums;
    cudaGetSymbolAddress((void**)&hsums, g_hsums);

    dim3 gridA(H, BATCH);
    hpass_kernel<<<gridA, HPB>>>(x, reinterpret_cast<uint4*>(hsums));

    dim3 gridB(XB4 * YCHUNKS, BATCH, NWIN);
    vpass_kernel<<<gridB, TPB>>>(hsums, k, R, out);
}

// round 15
// speedup vs baseline: 1.0656x; 1.0010x over previous
#include <cuda_runtime.h>
#include <cuda_fp16.h>
#include <math.h>

#define BATCH 8
#define H 1024
#define W 1024
#define NWIN 5
#define PADY 64
#define ROWS (H + 2 * PADY)   // 1152 rows per (win,batch) image in scratch
#define NIMG (NWIN * BATCH)   // 40

__device__ __constant__ int c_radii[NWIN] = {3, 7, 15, 31, 63};
// launch big windows first (z=0 -> w=4) so long blocks don't form a tail
__device__ __constant__ int c_worder[NWIN] = {4, 3, 2, 1, 0};

// Scratch: horizontal window sums (sum x, sum x^2) packed as half2, with
// PADY zero rows above and below each image so the vertical pass needs no
// bounds checks. Pad rows are NEVER written; __device__ globals are
// zero-initialized at module load, so they remain zero deterministically.
__device__ __half2 g_hsums[(size_t)NIMG * ROWS * W];

// ---------------------------------------------------------------------------
// Pass A: 256 threads, 4 consecutive pixels/thread. float4 load, per-thread
// serial prefix + warp scan + block combine. Prefix in smem padded every 16
// entries (conflict-free stride-4 reads). Each window emits 4 half2 pixels
// as one uint4 store. One block per (row, batch).
// ---------------------------------------------------------------------------
#define HPB 256
#define PIDX(e) ((e) + ((e) >> 4))

__global__ __launch_bounds__(HPB) void hpass_kernel(const float* __restrict__ x,
                                                    uint4* __restrict__ hsums) {
    const int y = blockIdx.x;
    const int b = blockIdx.y;
    const int t = threadIdx.x;
    const int lane = t & 31;
    const int wid = t >> 5;

    __shared__ float2 s_warp[8];
    __shared__ float2 s_pref[PIDX(W - 1) + 1];   // padded

    const float4 v4 = reinterpret_cast<const float4*>(
        x + ((size_t)b * H + y) * W)[t];

    float px0 = v4.x,        py0 = v4.x * v4.x;
    float px1 = px0 + v4.y,  py1 = py0 + v4.y * v4.y;
    float px2 = px1 + v4.z,  py2 = py1 + v4.z * v4.z;
    float px3 = px2 + v4.w,  py3 = py2 + v4.w * v4.w;

    float tx = px3, ty = py3;
#pragma unroll
    for (int off = 1; off < 32; off <<= 1) {
        float ax = __shfl_up_sync(0xffffffffu, tx, off);
        float ay = __shfl_up_sync(0xffffffffu, ty, off);
        if (lane >= off) { tx += ax; ty += ay; }
    }
    if (lane == 31) s_warp[wid] = make_float2(tx, ty);
    __syncthreads();
    if (wid == 0 && lane < 8) {
        float2 w2 = s_warp[lane];
        float wx = w2.x, wy = w2.y;
#pragma unroll
        for (int off = 1; off < 8; off <<= 1) {
            float ax = __shfl_up_sync(0xffu, wx, off);
            float ay = __shfl_up_sync(0xffu, wy, off);
            if (lane >= off) { wx += ax; wy += ay; }
        }
        s_warp[lane] = make_float2(wx, wy);
    }
    __syncthreads();

    float bx = tx - px3, by = ty - py3;
    if (wid > 0) {
        float2 wb = s_warp[wid - 1];
        bx += wb.x; by += wb.y;
    }

    const int q0 = 4 * t;
    s_pref[PIDX(q0 + 0)] = make_float2(bx + px0, by + py0);
    s_pref[PIDX(q0 + 1)] = make_float2(bx + px1, by + py1);
    s_pref[PIDX(q0 + 2)] = make_float2(bx + px2, by + py2);
    s_pref[PIDX(q0 + 3)] = make_float2(bx + px3, by + py3);
    __syncthreads();

#pragma unroll
    for (int w = 0; w < NWIN; w++) {
        const int r = c_radii[w];
        unsigned int h[4];
#pragma unroll
        for (int i = 0; i < 4; i++) {
            const int q = q0 + i;
            const int hi = min(q + r, W - 1);
            float2 s = s_pref[PIDX(hi)];
            if (q > r) {
                float2 p = s_pref[PIDX(q - r - 1)];
                s.x -= p.x; s.y -= p.y;
            }
            __half2 hh = __floats2half2_rn(s.x, s.y);
            h[i] = *reinterpret_cast<unsigned int*>(&hh);
        }
        uint4 pack = make_uint4(h[0], h[1], h[2], h[3]);
        hsums[((size_t)(w * BATCH + b) * ROWS + PADY + y) * (W / 4) + t] = pack;
    }
}

// ---------------------------------------------------------------------------
// Pass B: vertical sliding window + Sauvola epilogue (R8 structure/math).
// Each thread owns 2 adjacent columns (8B uint2 loads); batches of BU=4 rows
// load into register arrays first (8 loads in flight), then math. BU=4 keeps
// the load buffers at 16 regs so the kernel genuinely fits the regs<=48
// budget imposed by __launch_bounds__(128, 10) WITHOUT spilling (R14's
// regs=48 + BU=8 spilled ~70MB to local). Occupancy cap: 40 warps/SM.
// ---------------------------------------------------------------------------
#define TPB 128
#define XB4 (W / (2 * TPB))   // 4
#define YCHUNKS 16
#define YCHUNK (H / YCHUNKS)  // 64
#define BU 4                  // row batch (YCHUNK % BU == 0)

__global__ __launch_bounds__(TPB, 10) void vpass_kernel(const __half2* __restrict__ hsums,
                                                        const float* __restrict__ kk,
                                                        const float* __restrict__ RR,
                                                        float* __restrict__ out) {
    const int xblk = blockIdx.x & (XB4 - 1);
    const int ychunk = blockIdx.x / XB4;
    const int b = blockIdx.y;
    const int w = c_worder[blockIdx.z];

    const int tx = xblk * TPB + threadIdx.x;   // uint2 index (2 cols)
    const int x0 = 2 * tx;
    const int x1 = x0 + 1;
    const int r = c_radii[w];
    const float kw = kk[w];
    const float invR = __frcp_rn(RR[w]);

    const uint2* col = reinterpret_cast<const uint2*>(
        hsums + ((size_t)(w * BATCH + b) * ROWS + PADY) * W) + tx;
    float* o = out + (((size_t)b * NWIN + w) * H) * W + x0;

    const float cnth0 = (float)(min(x0 + r, W - 1) - max(x0 - r, 0) + 1);
    const float cnth1 = (float)(min(x1 + r, W - 1) - max(x1 - r, 0) + 1);

    const int y0 = ychunk * YCHUNK;

    float sx0 = 0.f, sy0 = 0.f, sx1 = 0.f, sy1 = 0.f;

    // Prime: S = sum of rows [y0-r, y0+r) (pad rows are zero, no clamping).
#pragma unroll 4
    for (int yy = y0 - r; yy < y0 + r; yy++) {
        uint2 u = col[(size_t)yy * (W / 2)];
        float2 f0 = __half22float2(*reinterpret_cast<__half2*>(&u.x));
        float2 f1 = __half22float2(*reinterpret_cast<__half2*>(&u.y));
        sx0 += f0.x; sy0 += f0.y; sx1 += f1.x; sy1 += f1.y;
    }

    for (int yb = y0; yb < y0 + YCHUNK; yb += BU) {
        // ---- batch-load phase: 2*BU independent 8B loads ----
        uint2 ua[BU], us[BU];
#pragma unroll
        for (int j = 0; j < BU; j++) {
            ua[j] = col[(size_t)(yb + j + r) * (W / 2)];
            us[j] = col[(size_t)(yb + j - r) * (W / 2)];
        }
        // ---- math phase ----
#pragma unroll
        for (int j = 0; j < BU; j++) {
            const int y = yb + j;
            {
                float2 f0 = __half22float2(*reinterpret_cast<__half2*>(&ua[j].x));
                float2 f1 = __half22float2(*reinterpret_cast<__half2*>(&ua[j].y));
                sx0 += f0.x; sy0 += f0.y; sx1 += f1.x; sy1 += f1.y;
            }
            const float cntv = (float)(min(y + r, H - 1) - max(y - r, 0) + 1);
            const float inv0 = __frcp_rn(cnth0 * cntv);
            const float inv1 = __frcp_rn(cnth1 * cntv);
            const float mean0 = sx0 * inv0, m20 = sy0 * inv0;
            const float mean1 = sx1 * inv1, m21 = sy1 * inv1;
            const float var0 = fmaxf(fmaf(-mean0, mean0, m20), 1e-6f);
            const float var1 = fmaxf(fmaf(-mean1, mean1, m21), 1e-6f);
            const float dev0 = sqrtf(var0);
            const float dev1 = sqrtf(var1);
            float2 res;
            res.x = mean0 * fmaf(kw, fmaf(dev0, invR, -1.0f), 1.0f);
            res.y = mean1 * fmaf(kw, fmaf(dev1, invR, -1.0f), 1.0f);
            *reinterpret_cast<float2*>(o + (size_t)y * W) = res;
            {
                float2 f0 = __half22float2(*reinterpret_cast<__half2*>(&us[j].x));
                float2 f1 = __half22float2(*reinterpret_cast<__half2*>(&us[j].y));
                sx0 -= f0.x; sy0 -= f0.y; sx1 -= f1.x; sy1 -= f1.y;
            }
        }
    }
}

extern "C" void kernel_launch(void* const* d_in, const int* in_sizes, int n_in,
                              void* d_out, int out_size) {
    const float* x = (const float*)d_in[0];
    const float* k = (const float*)d_in[1];
    const float* R = (const float*)d_in[2];
    float* out = (float*)d_out;

    __half2* hsums;
    cudaGetSymbolAddress((void**)&hsums, g_hsums);

    dim3 gridA(H, BATCH);
    hpass_kernel<<<gridA, HPB>>>(x, reinterpret_cast<uint4*>(hsums));

    dim3 gridB(XB4 * YCHUNKS, BATCH, NWIN);
    vpass_kernel<<<gridB, TPB>>>(hsums, k, R, out);
}

// round 16
// speedup vs baseline: 1.0839x; 1.0172x over previous
#include <cuda_runtime.h>
#include <cuda_fp16.h>
#include <math.h>

#define BATCH 8
#define H 1024
#define W 1024
#define NWIN 5
#define PADY 64
#define ROWS (H + 2 * PADY)   // 1152 rows per (win,batch) image in scratch
#define NIMG (NWIN * BATCH)   // 40

__device__ __constant__ int c_radii[NWIN] = {3, 7, 15, 31, 63};
// launch big windows first (z=0 -> w=4) so long blocks don't form a tail
__device__ __constant__ int c_worder[NWIN] = {4, 3, 2, 1, 0};

// Scratch: horizontal window sums (sum x, sum x^2) packed as half2, with
// PADY zero rows above and below each image so the vertical pass needs no
// bounds checks. Pad rows are NEVER written; __device__ globals are
// zero-initialized at module load, so they remain zero deterministically.
__device__ __half2 g_hsums[(size_t)NIMG * ROWS * W];

// ---------------------------------------------------------------------------
// Pass A: 256 threads, 4 consecutive pixels/thread. float4 load, per-thread
// serial prefix + warp scan + block combine. Prefix in smem padded every 16
// entries (conflict-free stride-4 reads). Each window emits 4 half2 pixels
// as one uint4 store. One block per (row, batch).
// ---------------------------------------------------------------------------
#define HPB 256
#define PIDX(e) ((e) + ((e) >> 4))

__global__ __launch_bounds__(HPB) void hpass_kernel(const float* __restrict__ x,
                                                    uint4* __restrict__ hsums) {
    const int y = blockIdx.x;
    const int b = blockIdx.y;
    const int t = threadIdx.x;
    const int lane = t & 31;
    const int wid = t >> 5;

    __shared__ float2 s_warp[8];
    __shared__ float2 s_pref[PIDX(W - 1) + 1];   // padded

    const float4 v4 = reinterpret_cast<const float4*>(
        x + ((size_t)b * H + y) * W)[t];

    float px0 = v4.x,        py0 = v4.x * v4.x;
    float px1 = px0 + v4.y,  py1 = py0 + v4.y * v4.y;
    float px2 = px1 + v4.z,  py2 = py1 + v4.z * v4.z;
    float px3 = px2 + v4.w,  py3 = py2 + v4.w * v4.w;

    float tx = px3, ty = py3;
#pragma unroll
    for (int off = 1; off < 32; off <<= 1) {
        float ax = __shfl_up_sync(0xffffffffu, tx, off);
        float ay = __shfl_up_sync(0xffffffffu, ty, off);
        if (lane >= off) { tx += ax; ty += ay; }
    }
    if (lane == 31) s_warp[wid] = make_float2(tx, ty);
    __syncthreads();
    if (wid == 0 && lane < 8) {
        float2 w2 = s_warp[lane];
        float wx = w2.x, wy = w2.y;
#pragma unroll
        for (int off = 1; off < 8; off <<= 1) {
            float ax = __shfl_up_sync(0xffu, wx, off);
            float ay = __shfl_up_sync(0xffu, wy, off);
            if (lane >= off) { wx += ax; wy += ay; }
        }
        s_warp[lane] = make_float2(wx, wy);
    }
    __syncthreads();

    float bx = tx - px3, by = ty - py3;
    if (wid > 0) {
        float2 wb = s_warp[wid - 1];
        bx += wb.x; by += wb.y;
    }

    const int q0 = 4 * t;
    s_pref[PIDX(q0 + 0)] = make_float2(bx + px0, by + py0);
    s_pref[PIDX(q0 + 1)] = make_float2(bx + px1, by + py1);
    s_pref[PIDX(q0 + 2)] = make_float2(bx + px2, by + py2);
    s_pref[PIDX(q0 + 3)] = make_float2(bx + px3, by + py3);
    __syncthreads();

#pragma unroll
    for (int w = 0; w < NWIN; w++) {
        const int r = c_radii[w];
        unsigned int h[4];
#pragma unroll
        for (int i = 0; i < 4; i++) {
            const int q = q0 + i;
            const int hi = min(q + r, W - 1);
            float2 s = s_pref[PIDX(hi)];
            if (q > r) {
                float2 p = s_pref[PIDX(q - r - 1)];
                s.x -= p.x; s.y -= p.y;
            }
            __half2 hh = __floats2half2_rn(s.x, s.y);
            h[i] = *reinterpret_cast<unsigned int*>(&hh);
        }
        uint4 pack = make_uint4(h[0], h[1], h[2], h[3]);
        hsums[((size_t)(w * BATCH + b) * ROWS + PADY + y) * (W / 4) + t] = pack;
    }
}

// ---------------------------------------------------------------------------
// Pass B: vertical sliding window + Sauvola epilogue (R15 structure/math).
// Pointer-walking streams: add / sub / out pointers advance by a constant
// per batch; in-batch offsets are compile-time (j*512) so SASS uses
// immediate-offset LDG/STG with no per-access address math.
// ---------------------------------------------------------------------------
#define TPB 128
#define XB4 (W / (2 * TPB))   // 4
#define YCHUNKS 16
#define YCHUNK (H / YCHUNKS)  // 64
#define BU 4                  // row batch (YCHUNK % BU == 0)
#define RSTRIDE (W / 2)       // 512 uint2 per row

__global__ __launch_bounds__(TPB, 10) void vpass_kernel(const __half2* __restrict__ hsums,
                                                        const float* __restrict__ kk,
                                                        const float* __restrict__ RR,
                                                        float* __restrict__ out) {
    const int xblk = blockIdx.x & (XB4 - 1);
    const int ychunk = blockIdx.x / XB4;
    const int b = blockIdx.y;
    const int w = c_worder[blockIdx.z];

    const int tx = xblk * TPB + threadIdx.x;   // uint2 index (2 cols)
    const int x0 = 2 * tx;
    const int x1 = x0 + 1;
    const int r = c_radii[w];
    const float kw = kk[w];
    const float invR = __frcp_rn(RR[w]);

    const uint2* col = reinterpret_cast<const uint2*>(
        hsums + ((size_t)(w * BATCH + b) * ROWS + PADY) * W) + tx;
    float2* po = reinterpret_cast<float2*>(
        out + (((size_t)b * NWIN + w) * H + (size_t)(ychunk * YCHUNK)) * W) + tx;

    const float cnth0 = (float)(min(x0 + r, W - 1) - max(x0 - r, 0) + 1);
    const float cnth1 = (float)(min(x1 + r, W - 1) - max(x1 - r, 0) + 1);

    const int y0 = ychunk * YCHUNK;

    float sx0 = 0.f, sy0 = 0.f, sx1 = 0.f, sy1 = 0.f;

    // Prime: S = sum of rows [y0-r, y0+r) (pad rows are zero, no clamping).
    const uint2* pp = col + (ptrdiff_t)(y0 - r) * RSTRIDE;
#pragma unroll 4
    for (int i = 0; i < 2 * r; i++) {
        uint2 u = *pp;
        pp += RSTRIDE;
        float2 f0 = __half22float2(*reinterpret_cast<__half2*>(&u.x));
        float2 f1 = __half22float2(*reinterpret_cast<__half2*>(&u.y));
        sx0 += f0.x; sy0 += f0.y; sx1 += f1.x; sy1 += f1.y;
    }

    const uint2* pa = col + (ptrdiff_t)(y0 + r) * RSTRIDE;   // add stream
    const uint2* ps = col + (ptrdiff_t)(y0 - r) * RSTRIDE;   // sub stream

    for (int yb = y0; yb < y0 + YCHUNK; yb += BU) {
        // ---- batch-load phase: 2*BU loads at immediate offsets ----
        uint2 ua[BU], us[BU];
#pragma unroll
        for (int j = 0; j < BU; j++) {
            ua[j] = pa[j * RSTRIDE];
            us[j] = ps[j * RSTRIDE];
        }
        pa += BU * RSTRIDE;
        ps += BU * RSTRIDE;
        // ---- math phase ----
#pragma unroll
        for (int j = 0; j < BU; j++) {
            const int y = yb + j;
            {
                float2 f0 = __half22float2(*reinterpret_cast<__half2*>(&ua[j].x));
                float2 f1 = __half22float2(*reinterpret_cast<__half2*>(&ua[j].y));
                sx0 += f0.x; sy0 += f0.y; sx1 += f1.x; sy1 += f1.y;
            }
            const float cntv = (float)(min(y + r, H - 1) - max(y - r, 0) + 1);
            const float inv0 = __frcp_rn(cnth0 * cntv);
            const float inv1 = __frcp_rn(cnth1 * cntv);
            const float mean0 = sx0 * inv0, m20 = sy0 * inv0;
            const float mean1 = sx1 * inv1, m21 = sy1 * inv1;
            const float var0 = fmaxf(fmaf(-mean0, mean0, m20), 1e-6f);
            const float var1 = fmaxf(fmaf(-mean1, mean1, m21), 1e-6f);
            const float dev0 = sqrtf(var0);
            const float dev1 = sqrtf(var1);
            float2 res;
            res.x = mean0 * fmaf(kw, fmaf(dev0, invR, -1.0f), 1.0f);
            res.y = mean1 * fmaf(kw, fmaf(dev1, invR, -1.0f), 1.0f);
            po[j * RSTRIDE] = res;
            {
                float2 f0 = __half22float2(*reinterpret_cast<__half2*>(&us[j].x));
                float2 f1 = __half22float2(*reinterpret_cast<__half2*>(&us[j].y));
                sx0 -= f0.x; sy0 -= f0.y; sx1 -= f1.x; sy1 -= f1.y;
            }
        }
        po += BU * RSTRIDE;
    }
}

extern "C" void kernel_launch(void* const* d_in, const int* in_sizes, int n_in,
                              void* d_out, int out_size) {
    const float* x = (const float*)d_in[0];
    const float* k = (const float*)d_in[1];
    const float* R = (const float*)d_in[2];
    float* out = (float*)d_out;

    __half2* hsums;
    cudaGetSymbolAddress((void**)&hsums, g_hsums);

    dim3 gridA(H, BATCH);
    hpass_kernel<<<gridA, HPB>>>(x, reinterpret_cast<uint4*>(hsums));

    dim3 gridB(XB4 * YCHUNKS, BATCH, NWIN);
    vpass_kernel<<<gridB, TPB>>>(hsums, k, R, out);
}